// round 1
// baseline (speedup 1.0000x reference)
#include <cuda_runtime.h>
#include <cuda_bf16.h>

// Snack: out[p] = tanh( (f[i]-f[j])^T M (f[i]-f[j]) ) for P = 8,388,608 pairs.
// Only 20 amino acids -> 400 distinct answers. Each block builds the 400-entry
// table in shared memory (trivial compute), then the kernel is a pure
// bandwidth-bound gather: 12 bytes of HBM traffic per pair.

#define NUM_AA   20
#define FEAT_DIM 16
#define TBL      (NUM_AA * NUM_AA)

__global__ __launch_bounds__(256) void snack_kernel(
    const float*  __restrict__ features,   // [20, 16]
    const float*  __restrict__ M,          // [16, 16]
    const int4*   __restrict__ idx_i4,     // [P/4]
    const int4*   __restrict__ idx_j4,     // [P/4]
    float4*       __restrict__ out4,       // [P/4]
    int n4)
{
    __shared__ float s_feat[NUM_AA * FEAT_DIM];  // 320 floats
    __shared__ float s_M[FEAT_DIM * FEAT_DIM];   // 256 floats
    __shared__ float s_tbl[TBL];                 // 400 floats

    const int t = threadIdx.x;

    // Stage features + M into shared memory.
    for (int k = t; k < NUM_AA * FEAT_DIM; k += blockDim.x) s_feat[k] = features[k];
    for (int k = t; k < FEAT_DIM * FEAT_DIM; k += blockDim.x) s_M[k] = M[k];
    __syncthreads();

    // Build the 400-entry table. ~2 entries/thread, ~512 FMA each: negligible.
    for (int e = t; e < TBL; e += blockDim.x) {
        const int i = e / NUM_AA;
        const int j = e % NUM_AA;
        float d[FEAT_DIM];
#pragma unroll
        for (int x = 0; x < FEAT_DIM; x++)
            d[x] = s_feat[i * FEAT_DIM + x] - s_feat[j * FEAT_DIM + x];
        float dist = 0.0f;
#pragma unroll
        for (int x = 0; x < FEAT_DIM; x++) {
            float mv = 0.0f;
#pragma unroll
            for (int y = 0; y < FEAT_DIM; y++)
                mv = fmaf(s_M[x * FEAT_DIM + y], d[y], mv);
            dist = fmaf(d[x], mv, dist);
        }
        s_tbl[e] = tanhf(dist);
    }
    __syncthreads();

    // Bandwidth-bound gather, 128-bit accesses.
    const int stride = gridDim.x * blockDim.x;
    for (int p = blockIdx.x * blockDim.x + t; p < n4; p += stride) {
        const int4 a = idx_i4[p];
        const int4 b = idx_j4[p];
        float4 o;
        o.x = s_tbl[a.x * NUM_AA + b.x];
        o.y = s_tbl[a.y * NUM_AA + b.y];
        o.z = s_tbl[a.z * NUM_AA + b.z];
        o.w = s_tbl[a.w * NUM_AA + b.w];
        out4[p] = o;
    }
}

extern "C" void kernel_launch(void* const* d_in, const int* in_sizes, int n_in,
                              void* d_out, int out_size)
{
    const float* features = (const float*)d_in[0];   // [20,16]
    const float* M        = (const float*)d_in[1];   // [16,16]
    const int*   idx_i    = (const int*)d_in[2];     // [P]
    const int*   idx_j    = (const int*)d_in[3];     // [P]
    float*       out      = (float*)d_out;           // [P]

    const int P  = out_size;          // 8,388,608
    const int n4 = P / 4;             // divisible by 4

    const int threads = 256;
    // Enough CTAs to saturate HBM across 148 SMs with a few waves.
    int blocks = (n4 + threads - 1) / threads;
    if (blocks > 2048) blocks = 2048;

    snack_kernel<<<blocks, threads>>>(
        features, M,
        (const int4*)idx_i, (const int4*)idx_j,
        (float4*)out, n4);
}

// round 2
// speedup vs baseline: 3.4260x; 3.4260x over previous
#include <cuda_runtime.h>
#include <cuda_bf16.h>

// Snack: out[p] = tanh((f[i]-f[j])^T M (f[i]-f[j])), P = 8,388,608, 20 AAs.
// Two kernels:
//   1) build 400-entry tanh table (trivial, one block)
//   2) lean bandwidth-bound gather through an smem copy of the table
// Traffic floor: 12 B/pair = 100.7 MB -> ~13us at 8 TB/s.

#define NUM_AA   20
#define FEAT_DIM 16
#define TBL      (NUM_AA * NUM_AA)

__device__ float g_tbl[TBL];

__global__ void build_table_kernel(const float* __restrict__ features,
                                   const float* __restrict__ M)
{
    const int e = blockIdx.x * blockDim.x + threadIdx.x;
    if (e >= TBL) return;
    const int i = e / NUM_AA;
    const int j = e % NUM_AA;
    float d[FEAT_DIM];
#pragma unroll
    for (int x = 0; x < FEAT_DIM; x++)
        d[x] = features[i * FEAT_DIM + x] - features[j * FEAT_DIM + x];
    float dist = 0.0f;
#pragma unroll
    for (int x = 0; x < FEAT_DIM; x++) {
        float mv = 0.0f;
#pragma unroll
        for (int y = 0; y < FEAT_DIM; y++)
            mv = fmaf(M[x * FEAT_DIM + y], d[y], mv);
        dist = fmaf(d[x], mv, dist);
    }
    g_tbl[e] = tanhf(dist);
}

// Each block processes ILP * 256 int4 elements (no loop, exact-fit grid).
#define ILP 4

__global__ __launch_bounds__(256) void gather_kernel(
    const int4*   __restrict__ idx_i4,
    const int4*   __restrict__ idx_j4,
    float4*       __restrict__ out4,
    int n4)
{
    __shared__ float s_tbl[TBL];
    for (int k = threadIdx.x; k < TBL; k += blockDim.x) s_tbl[k] = g_tbl[k];
    __syncthreads();

    const int base = blockIdx.x * (256 * ILP) + threadIdx.x;

    int4 a[ILP], b[ILP];
#pragma unroll
    for (int u = 0; u < ILP; u++) {
        const int p = base + u * 256;
        if (p < n4) {
            a[u] = idx_i4[p];
            b[u] = idx_j4[p];
        }
    }
#pragma unroll
    for (int u = 0; u < ILP; u++) {
        const int p = base + u * 256;
        if (p < n4) {
            float4 o;
            o.x = s_tbl[a[u].x * NUM_AA + b[u].x];
            o.y = s_tbl[a[u].y * NUM_AA + b[u].y];
            o.z = s_tbl[a[u].z * NUM_AA + b[u].z];
            o.w = s_tbl[a[u].w * NUM_AA + b[u].w];
            out4[p] = o;
        }
    }
}

extern "C" void kernel_launch(void* const* d_in, const int* in_sizes, int n_in,
                              void* d_out, int out_size)
{
    const float* features = (const float*)d_in[0];   // [20,16]
    const float* M        = (const float*)d_in[1];   // [16,16]
    const int*   idx_i    = (const int*)d_in[2];     // [P]
    const int*   idx_j    = (const int*)d_in[3];     // [P]
    float*       out      = (float*)d_out;           // [P]

    const int P  = out_size;   // 8,388,608
    const int n4 = P / 4;      // 2,097,152

    build_table_kernel<<<1, 512>>>(features, M);

    const int per_block = 256 * ILP;
    const int blocks = (n4 + per_block - 1) / per_block;   // 2048
    gather_kernel<<<blocks, 256>>>(
        (const int4*)idx_i, (const int4*)idx_j, (float4*)out, n4);
}